// round 14
// baseline (speedup 1.0000x reference)
#include <cuda_runtime.h>
#include <cuda_fp16.h>

#define BB   8
#define CC   64
#define TT   192
#define FFR  128
#define LTm  192
#define LFm  128
#define NEL  (BB*CC*TT*FFR)
#define HH   4

#define SEGS_T  16             // KSEG 512
#define SEGS_F  12             // KSEG 1024
#define NBLK_T  (SEGS_T*16)    // 256
#define NBLK_F  (SEGS_F*16)    // 192
#define NT_E    (16*LTm*LTm)
#define NF_E    (16*LFm*LFm)

typedef unsigned short ush;

// ---------------- scratch ----------------
__device__ ush g_Nh[2][NEL], g_Nl[2][NEL];      // time view chunks [b][kchunk][t(192)][32] (fp16)
__device__ ush g_Th[2][NEL], g_Tl[2][NEL];      // freq view chunks [b][kchunk][f(128)][32] (fp16)
__device__ float g_GpT[SEGS_T][16][LTm*LTm];
__device__ float g_GpF[SEGS_F][16][LFm*LFm];
__device__ float g_G[2][2][BB*LTm*LTm];
__device__ float g_inv[2][2][BB*LTm];
__device__ float g_mean[2][2][BB*LTm];
__device__ float g_ent[2][BB*LTm];
__device__ float g_rowdot[2][BB*LTm];
__device__ float g_part[2][512];

// ---------------- helpers ----------------
__device__ __forceinline__ float warpSum(float v) {
#pragma unroll
    for (int o = 16; o; o >>= 1) v += __shfl_xor_sync(0xffffffffu, v, o);
    return v;
}
__device__ __forceinline__ float warpMax(float v) {
#pragma unroll
    for (int o = 16; o; o >>= 1) v = fmaxf(v, __shfl_xor_sync(0xffffffffu, v, o));
    return v;
}
__device__ __forceinline__ float blockSum(float v, float* sm) {
    v = warpSum(v);
    int w = threadIdx.x >> 5;
    __syncthreads();
    if ((threadIdx.x & 31) == 0) sm[w] = v;
    __syncthreads();
    float r = 0.f;
    int nw = (blockDim.x + 31) >> 5;
    for (int i = 0; i < nw; i++) r += sm[i];
    return r;
}
__device__ __forceinline__ float blockMax(float v, float* sm) {
    v = warpMax(v);
    int w = threadIdx.x >> 5;
    __syncthreads();
    if ((threadIdx.x & 31) == 0) sm[w] = v;
    __syncthreads();
    float r = -3.402823466e38f;
    int nw = (blockDim.x + 31) >> 5;
    for (int i = 0; i < nw; i++) r = fmaxf(r, sm[i]);
    return r;
}
__device__ __forceinline__ void pack8(const float* x, uint4& H, uint4& L) {
    unsigned hw[4], lw[4];
#pragma unroll
    for (int m = 0; m < 4; m++) {
        __half2 h2 = __floats2half2_rn(x[2 * m], x[2 * m + 1]);
        float l0 = x[2 * m]     - __half2float(__low2half(h2));
        float l1 = x[2 * m + 1] - __half2float(__high2half(h2));
        __half2 l2 = __floats2half2_rn(l0, l1);
        hw[m] = *(unsigned*)&h2;
        lw[m] = *(unsigned*)&l2;
    }
    H = make_uint4(hw[0], hw[1], hw[2], hw[3]);
    L = make_uint4(lw[0], lw[1], lw[2], lw[3]);
}
__device__ __forceinline__ void ldsm4(unsigned* r, unsigned a) {
    asm volatile("ldmatrix.sync.aligned.m8n8.x4.shared.b16 {%0,%1,%2,%3}, [%4];"
                 : "=r"(r[0]), "=r"(r[1]), "=r"(r[2]), "=r"(r[3]) : "r"(a));
}
__device__ __forceinline__ void mma16816(float* d, const unsigned* a, unsigned b0, unsigned b1) {
    asm volatile("mma.sync.aligned.m16n8k16.row.col.f32.f16.f16.f32 "
                 "{%0,%1,%2,%3}, {%4,%5,%6,%7}, {%8,%9}, {%0,%1,%2,%3};"
                 : "+f"(d[0]), "+f"(d[1]), "+f"(d[2]), "+f"(d[3])
                 : "r"(a[0]), "r"(a[1]), "r"(a[2]), "r"(a[3]), "r"(b0), "r"(b1));
}
__device__ __forceinline__ unsigned swa(unsigned base, int row, int kbyte) {
    return base + row * 64 + (((((unsigned)kbyte >> 4) ^ (((unsigned)row >> 1) & 3u)) & 3u) << 4);
}
__device__ __forceinline__ void cpa16(unsigned dst, const void* src) {
    asm volatile("cp.async.cg.shared.global [%0], [%1], 16;" :: "r"(dst), "l"(src) : "memory");
}
__device__ __forceinline__ void mlp4(float x, const float* __restrict__ W,
                                     const float* __restrict__ bi,
                                     const float* __restrict__ g,
                                     const float* __restrict__ be, float* o) {
    float h[HH]; float mu = 0.f;
#pragma unroll
    for (int j = 0; j < HH; j++) { h[j] = fmaxf(W[j] * x + bi[j], 0.f); mu += h[j]; }
    mu *= (1.0f / HH);
    float var = 0.f;
#pragma unroll
    for (int j = 0; j < HH; j++) { float d = h[j] - mu; var += d * d; }
    var *= (1.0f / HH);
    float inv = rsqrtf(var + 1e-5f);
#pragma unroll
    for (int j = 0; j < HH; j++) o[j] = g[j] * (h[j] - mu) * inv + be[j];
}

// ---------------- 1) prep: fp32 -> chunked fp16 hi/lo, both views ----------------
__global__ void prep_kernel(const float* __restrict__ fs, const float* __restrict__ ft) {
    __shared__ float tile[32][33];
    int z = blockIdx.z;
    int which = z >> 9, bc = z & 511;
    int b = bc >> 6, c = bc & 63;
    const float* src = (which ? ft : fs) + (size_t)bc * TT * FFR;
    int t0 = blockIdx.x * 32, f0 = blockIdx.y * 32;
    int tx = threadIdx.x, ty = threadIdx.y;
#pragma unroll
    for (int i = 0; i < 32; i += 8)
        tile[ty + i][tx] = src[(size_t)(t0 + ty + i) * FFR + f0 + tx];
    __syncthreads();
    int tid = ty * 32 + tx;
    float x[8];
    uint4 Hv, Lv;
    if (tid < 128) {
        int tl = tid >> 2, fg = tid & 3;
#pragma unroll
        for (int j = 0; j < 8; j++) x[j] = tile[tl][fg * 8 + j];
        pack8(x, Hv, Lv);
        size_t o = (((size_t)(bc * 4 + (f0 >> 5)) * 192) + (t0 + tl)) * 32 + fg * 8;
        *(uint4*)(&g_Nh[which][o]) = Hv;
        *(uint4*)(&g_Nl[which][o]) = Lv;
    } else {
        int it = tid - 128;
        int tg = it & 3, fl = it >> 2;
#pragma unroll
        for (int j = 0; j < 8; j++) x[j] = tile[tg * 8 + j][fl];
        pack8(x, Hv, Lv);
        size_t o = (((size_t)(b * 384 + c * 6 + (t0 >> 5)) * 128) + (f0 + fl)) * 32 + tg * 8;
        *(uint4*)(&g_Th[which][o]) = Hv;
        *(uint4*)(&g_Tl[which][o]) = Lv;
    }
}

// ---------------- 2) merged-triangle gram: all L rows staged once, 12 warps ----------------
// Tiles: D1 (0,0), O (0,TM), D2 (TM,TM); 4 warps each, (TM/2)x(TM/2) per warp.
// fp16 2-split: G_tile = HH + HL per tile.
template<int L, int TM, int MI, int NPg, int NCH>
__device__ __forceinline__ void gram3_body(const ush* gh, const ush* gl,
                                           float* __restrict__ Gp, unsigned sb)
{
    constexpr int TILEB = L * 64;       // bytes per array per stage
    constexpr int STG = 2 * TILEB;      // hi + lo
    int tid = threadIdx.x, wid = tid >> 5, lane = tid & 31;
    int t8 = lane >> 3, r8 = lane & 7;
    int aro = r8 + (t8 & 1) * 8, ako = (t8 >> 1) * 16;
    int bro = r8 + (t8 >> 1) * 8, bko = (t8 & 1) * 16;
    int wtile = wid >> 2, sub = wid & 3;
    int m0w = (wtile == 2 ? TM : 0) + (sub >> 1) * (TM / 2);
    int j0w = (wtile == 0 ? 0 : TM) + (sub & 1) * (TM / 2);

    float acc[MI][2 * NPg][4];
#pragma unroll
    for (int mi = 0; mi < MI; mi++)
#pragma unroll
        for (int n = 0; n < 2 * NPg; n++)
#pragma unroll
            for (int u = 0; u < 4; u++) acc[mi][n][u] = 0.f;

    auto copy_chunk = [&](int ch) {
        unsigned dst = sb + (unsigned)(ch & 1) * STG;
        const ush* sh = gh + (size_t)ch * L * 32;
        const ush* sl = gl + (size_t)ch * L * 32;
#pragma unroll
        for (int i = 0; i < 2; i++) {
            int lin = i * 384 + tid;
            if (lin < L * 4) {
                int row = lin >> 2, q = lin & 3;
                unsigned d = dst + (unsigned)(row * 64 + ((q ^ ((row >> 1) & 3)) << 4));
                cpa16(d, sh + row * 32 + q * 8);
                cpa16(d + TILEB, sl + row * 32 + q * 8);
            }
        }
        asm volatile("cp.async.commit_group;" ::: "memory");
    };

    copy_chunk(0);
    for (int ch = 0; ch < NCH; ch++) {
        if (ch < NCH - 1) {
            copy_chunk(ch + 1);
            asm volatile("cp.async.wait_group 1;" ::: "memory");
        } else {
            asm volatile("cp.async.wait_group 0;" ::: "memory");
        }
        __syncthreads();
        unsigned hb = sb + (unsigned)(ch & 1) * STG;
        unsigned lb = hb + TILEB;

#pragma unroll
        for (int ks = 0; ks < 2; ks++) {
            int kb = ks * 32;
            unsigned ah[MI][4], bh[NPg][4];
#pragma unroll
            for (int mi = 0; mi < MI; mi++) ldsm4(ah[mi], swa(hb, m0w + mi * 16 + aro, kb + ako));
#pragma unroll
            for (int nj = 0; nj < NPg; nj++) ldsm4(bh[nj], swa(hb, j0w + nj * 16 + bro, kb + bko));
#pragma unroll
            for (int mi = 0; mi < MI; mi++)
#pragma unroll
                for (int nj = 0; nj < NPg; nj++) {
                    mma16816(acc[mi][2 * nj],     ah[mi], bh[nj][0], bh[nj][1]);
                    mma16816(acc[mi][2 * nj + 1], ah[mi], bh[nj][2], bh[nj][3]);
                }
            unsigned bl[NPg][4];
#pragma unroll
            for (int nj = 0; nj < NPg; nj++) ldsm4(bl[nj], swa(lb, j0w + nj * 16 + bro, kb + bko));
#pragma unroll
            for (int mi = 0; mi < MI; mi++)
#pragma unroll
                for (int nj = 0; nj < NPg; nj++) {
                    mma16816(acc[mi][2 * nj],     ah[mi], bl[nj][0], bl[nj][1]);
                    mma16816(acc[mi][2 * nj + 1], ah[mi], bl[nj][2], bl[nj][3]);
                }
        }
        __syncthreads();
    }

    int rq = lane >> 2, cq = lane & 3;
#pragma unroll
    for (int mi = 0; mi < MI; mi++)
#pragma unroll
        for (int n = 0; n < 2 * NPg; n++) {
            int m = m0w + mi * 16 + rq, j = j0w + n * 8 + cq * 2;
            *(float2*)&Gp[(size_t)m * L + j] = make_float2(acc[mi][n][0], acc[mi][n][1]);
            *(float2*)&Gp[(size_t)(m + 8) * L + j] = make_float2(acc[mi][n][2], acc[mi][n][3]);
        }
}

__global__ void __launch_bounds__(384) gram_kernel() {
    extern __shared__ __align__(16) char smraw[];
    unsigned sb = (unsigned)__cvta_generic_to_shared(smraw);
    int bid = blockIdx.x;
    if (bid < NBLK_T) {
        int seg = bid >> 4, bw = bid & 15;
        int which = bw >> 3, b = bw & 7;
        const ush* gh = g_Nh[which] + (size_t)(b * 256 + seg * 16) * (LTm * 32);
        const ush* gl = g_Nl[which] + (size_t)(b * 256 + seg * 16) * (LTm * 32);
        gram3_body<LTm, 96, 3, 3, 16>(gh, gl, &g_GpT[seg][bw][0], sb);
    } else {
        int r = bid - NBLK_T;
        int seg = r >> 4, bw = r & 15;
        int which = bw >> 3, b = bw & 7;
        const ush* gh = g_Th[which] + (size_t)(b * 384 + seg * 32) * (LFm * 32);
        const ush* gl = g_Tl[which] + (size_t)(b * 384 + seg * 32) * (LFm * 32);
        gram3_body<LFm, 64, 2, 2, 32>(gh, gl, &g_GpF[seg][bw][0], sb);
    }
}

// ---------------- 3) sum partials + mirror + fused norms ----------------
__global__ void sumG_kernel() {
    int idx = blockIdx.x * 256 + threadIdx.x;
    if (idx < NT_E) {
        int bw = idx / (LTm * LTm), e = idx % (LTm * LTm);
        int i = e / LTm, j = e % LTm;
        int es = (i >= 96 && j < 96) ? (j * LTm + i) : e;
        float s = 0.f;
#pragma unroll
        for (int g = 0; g < SEGS_T; g++) s += g_GpT[g][bw][es];
        int which = bw >> 3, b = bw & 7;
        g_G[0][which][(size_t)b * LTm * LTm + e] = s;
        if (i == j) g_inv[0][which][b * LTm + i] = 1.0f / fmaxf(sqrtf(s), 1e-8f);
    } else {
        idx -= NT_E;
        int bw = idx / (LFm * LFm), e = idx % (LFm * LFm);
        int i = e / LFm, j = e % LFm;
        int es = (i >= 64 && j < 64) ? (j * LFm + i) : e;
        float s = 0.f;
#pragma unroll
        for (int g = 0; g < SEGS_F; g++) s += g_GpF[g][bw][es];
        int which = bw >> 3, b = bw & 7;
        g_G[1][which][(size_t)b * LFm * LFm + e] = s;
        if (i == j) g_inv[1][which][b * LFm + i] = 1.0f / fmaxf(sqrtf(s), 1e-8f);
    }
}

// ---------------- 4) rowproc: warp-per-row, both views, no barriers ----------------
__global__ void rowproc2_kernel() {
    int w = blockIdx.x * 8 + (threadIdx.x >> 5);
    int lane = threadIdx.x & 31;
    int view, which, b, l, L;
    if (w < 3072) { view = 0; L = 192; which = w / 1536; int r = w % 1536; b = r / 192; l = r % 192; }
    else { int w2 = w - 3072; view = 1; L = 128; which = w2 / 1024; int r = w2 % 1024; b = r / 128; l = r % 128; }
    float* G = g_G[view][which] + ((size_t)b * L + l) * L;
    const float* inv = g_inv[view][which] + b * L;
    float invl = inv[l];
    int ne = L >> 5;
    float pv[6];
    float s = 0.f, mx = -3.402823466e38f;
    for (int e = 0; e < ne; e++) {
        int m = lane + e * 32;
        pv[e] = 0.5f * (G[m] * invl * inv[m] + 1.0f);
        s += pv[e];
        mx = fmaxf(mx, pv[e]);
    }
    s = warpSum(s);
    mx = warpMax(mx);
    if (lane == 0) g_mean[view][which][b * L + l] = s / (float)L;
    float ex[6], Z = 0.f;
    for (int e = 0; e < ne; e++) { ex[e] = expf(pv[e] - mx); Z += ex[e]; }
    Z = warpSum(Z);
    float ent = 0.f;
    for (int e = 0; e < ne; e++) {
        int m = lane + e * 32;
        float sp = ex[e] / Z + 1e-8f;
        if (which == 0) G[m] = logf(sp + 1e-8f);
        else { G[m] = sp; ent += sp * logf(sp + 1e-8f); }
    }
    if (which == 1) {
        ent = warpSum(ent);
        if (lane == 0) g_ent[view][b * L + l] = ent;
    }
}

// ---------------- 5) part2: fused MLP + alpha + rowdot + term2 ----------------
__global__ void part2_kernel(const float* __restrict__ WqT, const float* __restrict__ bqT,
                             const float* __restrict__ gqT, const float* __restrict__ BqT,
                             const float* __restrict__ WkT, const float* __restrict__ bkT,
                             const float* __restrict__ gkT, const float* __restrict__ BkT,
                             const float* __restrict__ WqF, const float* __restrict__ bqF,
                             const float* __restrict__ gqF, const float* __restrict__ BqF,
                             const float* __restrict__ WkF, const float* __restrict__ bkF,
                             const float* __restrict__ gkF, const float* __restrict__ BkF) {
    __shared__ float kb[LTm * HH];
    __shared__ float salT[LTm][8];
    __shared__ float red[8];
    __shared__ float qv8[8][HH];
    int view = blockIdx.z, b = blockIdx.y;
    int L = view ? LFm : LTm;
    if (blockIdx.x * 8 >= L) {
        if (threadIdx.x == 0) g_part[view][b * 24 + blockIdx.x] = 0.f;
        return;
    }
    int s0 = blockIdx.x * 8;
    int t = threadIdx.x;
    const float* Wq = view ? WqF : WqT; const float* bq = view ? bqF : bqT;
    const float* gq = view ? gqF : gqT; const float* Bq = view ? BqF : BqT;
    const float* Wk = view ? WkF : WkT; const float* bk = view ? bkF : bkT;
    const float* gk = view ? gkF : gkT; const float* Bk = view ? BkF : BkT;

    if (t < L) {
        float kv[HH];
        mlp4(g_mean[view][1][b * L + t], Wk, bk, gk, Bk, kv);
#pragma unroll
        for (int j = 0; j < HH; j++) kb[t * HH + j] = kv[j];
    }
    if (t < 8) {
        float qv[HH];
        mlp4(g_mean[view][0][b * L + s0 + t], Wq, bq, gq, Bq, qv);
#pragma unroll
        for (int j = 0; j < HH; j++) qv8[t][j] = qv[j];
    }
    __syncthreads();

    float entt = (t < L) ? g_ent[view][b * L + t] : 0.f;
    float k0 = 0.f, k1 = 0.f, k2 = 0.f, k3 = 0.f;
    if (t < L) { k0 = kb[t * 4 + 0]; k1 = kb[t * 4 + 1]; k2 = kb[t * 4 + 2]; k3 = kb[t * 4 + 3]; }
    float invScale = rsqrtf(4.0f + 1e-8f);
#pragma unroll
    for (int i = 0; i < 8; i++) {
        float a = -3.402823466e38f;
        if (t < L)
            a = (qv8[i][0] * k0 + qv8[i][1] * k1 + qv8[i][2] * k2 + qv8[i][3] * k3) * invScale;
        float mx = blockMax(a, red);
        float e = (t < L) ? expf(a - mx) : 0.f;
        float Z = blockSum(e, red);
        float al = e / Z;
        if (t < L) salT[t][i] = al;
        float rd = blockSum(al * entt, red);
        if (t == 0) g_rowdot[view][b * L + s0 + i] = rd;
    }
    __syncthreads();

    const float* logPs = g_G[view][0] + (size_t)b * L * L;
    const float* Pt    = g_G[view][1] + (size_t)b * L * L;
    int k = t;
    float m[8];
#pragma unroll
    for (int i = 0; i < 8; i++) m[i] = 0.f;
    int kc = (k < L) ? k : 0;
#pragma unroll 2
    for (int tt = 0; tt < L; tt++) {
        float4 a0 = *(const float4*)&salT[tt][0];
        float4 a1 = *(const float4*)&salT[tt][4];
        float pv = Pt[(size_t)tt * L + kc];
        m[0] += a0.x * pv; m[1] += a0.y * pv; m[2] += a0.z * pv; m[3] += a0.w * pv;
        m[4] += a1.x * pv; m[5] += a1.y * pv; m[6] += a1.z * pv; m[7] += a1.w * pv;
    }
    float acc = 0.f;
    if (k < L) {
#pragma unroll
        for (int i = 0; i < 8; i++) acc += m[i] * logPs[(size_t)(s0 + i) * L + k];
    }
    float tot = blockSum(acc, red);
    if (k == 0) g_part[view][b * 24 + blockIdx.x] = tot;
}

// ---------------- 6) final reduction ----------------
__global__ void final_kernel(float* out) {
    __shared__ float red[8];
    int tid = threadIdx.x;
    float t2T = 0.f; for (int i = tid; i < 24 * BB; i += 256) t2T += g_part[0][i];
    t2T = blockSum(t2T, red);
    float t2F = 0.f; for (int i = tid; i < 24 * BB; i += 256) t2F += g_part[1][i];
    t2F = blockSum(t2F, red);
    float t1T = 0.f; for (int i = tid; i < BB * LTm; i += 256) t1T += g_rowdot[0][i];
    t1T = blockSum(t1T, red);
    float t1F = 0.f; for (int i = tid; i < BB * LFm; i += 256) t1F += g_rowdot[1][i];
    t1F = blockSum(t1F, red);
    if (tid == 0) {
        float lt = (t1T - t2T) / ((float)BB * LTm * LTm + 1e-8f);
        float lf = (t1F - t2F) / ((float)BB * LFm * LFm + 1e-8f);
        out[0] = lt + lf;
    }
}

// ---------------- launch ----------------
extern "C" void kernel_launch(void* const* d_in, const int* in_sizes, int n_in,
                              void* d_out, int out_size) {
    const float* fs  = (const float*)d_in[0];
    const float* ft  = (const float*)d_in[1];
    float* out = (float*)d_out;

    prep_kernel<<<dim3(TT / 32, FFR / 32, BB * CC * 2), dim3(32, 8)>>>(fs, ft);

    gram_kernel<<<NBLK_T + NBLK_F, 384, 49152>>>();

    sumG_kernel<<<(NT_E + NF_E) / 256, 256>>>();

    rowproc2_kernel<<<640, 256>>>();

    part2_kernel<<<dim3(24, BB, 2), 192>>>(
        (const float*)d_in[2], (const float*)d_in[3], (const float*)d_in[4], (const float*)d_in[5],
        (const float*)d_in[6], (const float*)d_in[7], (const float*)d_in[8], (const float*)d_in[9],
        (const float*)d_in[10], (const float*)d_in[11], (const float*)d_in[12], (const float*)d_in[13],
        (const float*)d_in[14], (const float*)d_in[15], (const float*)d_in[16], (const float*)d_in[17]);

    final_kernel<<<1, 256>>>(out);
}

// round 15
// speedup vs baseline: 1.1870x; 1.1870x over previous
#include <cuda_runtime.h>
#include <cuda_fp16.h>

#define BB   8
#define CC   64
#define TT   192
#define FFR  128
#define LTm  192
#define LFm  128
#define NEL  (BB*CC*TT*FFR)
#define HH   4

#define SEGS_T  8              // KSEG 1024
#define SEGS_F  6              // KSEG 2048
#define NBLK_T  (SEGS_T*16*3)  // 384
#define NBLK_F  (SEGS_F*16*3)  // 288
#define NT_E    (16*LTm*LTm)
#define NF_E    (16*LFm*LFm)

typedef unsigned short ush;

// ---------------- scratch ----------------
__device__ ush g_Nh[2][NEL], g_Nl[2][NEL];      // time view chunks [b][kchunk][t(192)][32] (fp16)
__device__ ush g_Th[2][NEL], g_Tl[2][NEL];      // freq view chunks [b][kchunk][f(128)][32] (fp16)
__device__ float g_GpT[SEGS_T][16][LTm*LTm];
__device__ float g_GpF[SEGS_F][16][LFm*LFm];
__device__ float g_G[2][2][BB*LTm*LTm];
__device__ float g_inv[2][2][BB*LTm];
__device__ float g_mean[2][2][BB*LTm];
__device__ float g_ent[2][BB*LTm];
__device__ float g_rowdot[2][BB*LTm];
__device__ float g_part[2][512];

// ---------------- helpers ----------------
__device__ __forceinline__ float warpSum(float v) {
#pragma unroll
    for (int o = 16; o; o >>= 1) v += __shfl_xor_sync(0xffffffffu, v, o);
    return v;
}
__device__ __forceinline__ float warpMax(float v) {
#pragma unroll
    for (int o = 16; o; o >>= 1) v = fmaxf(v, __shfl_xor_sync(0xffffffffu, v, o));
    return v;
}
__device__ __forceinline__ float blockSum(float v, float* sm) {
    v = warpSum(v);
    int w = threadIdx.x >> 5;
    __syncthreads();
    if ((threadIdx.x & 31) == 0) sm[w] = v;
    __syncthreads();
    float r = 0.f;
    int nw = (blockDim.x + 31) >> 5;
    for (int i = 0; i < nw; i++) r += sm[i];
    return r;
}
__device__ __forceinline__ float blockMax(float v, float* sm) {
    v = warpMax(v);
    int w = threadIdx.x >> 5;
    __syncthreads();
    if ((threadIdx.x & 31) == 0) sm[w] = v;
    __syncthreads();
    float r = -3.402823466e38f;
    int nw = (blockDim.x + 31) >> 5;
    for (int i = 0; i < nw; i++) r = fmaxf(r, sm[i]);
    return r;
}
__device__ __forceinline__ void pack8(const float* x, uint4& H, uint4& L) {
    unsigned hw[4], lw[4];
#pragma unroll
    for (int m = 0; m < 4; m++) {
        __half2 h2 = __floats2half2_rn(x[2 * m], x[2 * m + 1]);
        float l0 = x[2 * m]     - __half2float(__low2half(h2));
        float l1 = x[2 * m + 1] - __half2float(__high2half(h2));
        __half2 l2 = __floats2half2_rn(l0, l1);
        hw[m] = *(unsigned*)&h2;
        lw[m] = *(unsigned*)&l2;
    }
    H = make_uint4(hw[0], hw[1], hw[2], hw[3]);
    L = make_uint4(lw[0], lw[1], lw[2], lw[3]);
}
__device__ __forceinline__ void ldsm4(unsigned* r, unsigned a) {
    asm volatile("ldmatrix.sync.aligned.m8n8.x4.shared.b16 {%0,%1,%2,%3}, [%4];"
                 : "=r"(r[0]), "=r"(r[1]), "=r"(r[2]), "=r"(r[3]) : "r"(a));
}
__device__ __forceinline__ void mma16816(float* d, const unsigned* a, unsigned b0, unsigned b1) {
    asm volatile("mma.sync.aligned.m16n8k16.row.col.f32.f16.f16.f32 "
                 "{%0,%1,%2,%3}, {%4,%5,%6,%7}, {%8,%9}, {%0,%1,%2,%3};"
                 : "+f"(d[0]), "+f"(d[1]), "+f"(d[2]), "+f"(d[3])
                 : "r"(a[0]), "r"(a[1]), "r"(a[2]), "r"(a[3]), "r"(b0), "r"(b1));
}
__device__ __forceinline__ unsigned swa(unsigned base, int row, int kbyte) {
    return base + row * 64 + (((((unsigned)kbyte >> 4) ^ (((unsigned)row >> 1) & 3u)) & 3u) << 4);
}
__device__ __forceinline__ void cpa16(unsigned dst, const void* src) {
    asm volatile("cp.async.cg.shared.global [%0], [%1], 16;" :: "r"(dst), "l"(src) : "memory");
}
__device__ __forceinline__ void mlp4(float x, const float* __restrict__ W,
                                     const float* __restrict__ bi,
                                     const float* __restrict__ g,
                                     const float* __restrict__ be, float* o) {
    float h[HH]; float mu = 0.f;
#pragma unroll
    for (int j = 0; j < HH; j++) { h[j] = fmaxf(W[j] * x + bi[j], 0.f); mu += h[j]; }
    mu *= (1.0f / HH);
    float var = 0.f;
#pragma unroll
    for (int j = 0; j < HH; j++) { float d = h[j] - mu; var += d * d; }
    var *= (1.0f / HH);
    float inv = rsqrtf(var + 1e-5f);
#pragma unroll
    for (int j = 0; j < HH; j++) o[j] = g[j] * (h[j] - mu) * inv + be[j];
}

// ---------------- 1) prep: fp32 -> chunked fp16 hi/lo, both views ----------------
__global__ void prep_kernel(const float* __restrict__ fs, const float* __restrict__ ft) {
    __shared__ float tile[32][33];
    int z = blockIdx.z;
    int which = z >> 9, bc = z & 511;
    int b = bc >> 6, c = bc & 63;
    const float* src = (which ? ft : fs) + (size_t)bc * TT * FFR;
    int t0 = blockIdx.x * 32, f0 = blockIdx.y * 32;
    int tx = threadIdx.x, ty = threadIdx.y;
#pragma unroll
    for (int i = 0; i < 32; i += 8)
        tile[ty + i][tx] = src[(size_t)(t0 + ty + i) * FFR + f0 + tx];
    __syncthreads();
    int tid = ty * 32 + tx;
    float x[8];
    uint4 Hv, Lv;
    if (tid < 128) {
        int tl = tid >> 2, fg = tid & 3;
#pragma unroll
        for (int j = 0; j < 8; j++) x[j] = tile[tl][fg * 8 + j];
        pack8(x, Hv, Lv);
        size_t o = (((size_t)(bc * 4 + (f0 >> 5)) * 192) + (t0 + tl)) * 32 + fg * 8;
        *(uint4*)(&g_Nh[which][o]) = Hv;
        *(uint4*)(&g_Nl[which][o]) = Lv;
    } else {
        int it = tid - 128;
        int tg = it & 3, fl = it >> 2;
#pragma unroll
        for (int j = 0; j < 8; j++) x[j] = tile[tg * 8 + j][fl];
        pack8(x, Hv, Lv);
        size_t o = (((size_t)(b * 384 + c * 6 + (t0 >> 5)) * 128) + (f0 + fl)) * 32 + tg * 8;
        *(uint4*)(&g_Th[which][o]) = Hv;
        *(uint4*)(&g_Tl[which][o]) = Lv;
    }
}

// ---------------- 2) triangular-pair gram: fp16 2-split (HH + HL) ----------------
template<int L, int TM, int MI, int NP, int NCH, int PLD>
__device__ __forceinline__ void gram_body(const ush* gh, const ush* gl,
                                          int rows0, int rows1, bool diag,
                                          float* __restrict__ Gp, unsigned sb)
{
    constexpr int TMB = TM * 64;
    constexpr int BUFB = 4 * TMB;
    int tid = threadIdx.x, wid = tid >> 5, lane = tid & 31;
    int t8 = lane >> 3, r8 = lane & 7;
    int aro = r8 + (t8 & 1) * 8, ako = (t8 >> 1) * 16;
    int bro = r8 + (t8 >> 1) * 8, bko = (t8 & 1) * 16;
    int m0w = (wid >> 1) * (TM / 2), j0w = (wid & 1) * (TM / 2);

    float acc[MI][2 * NP][4];
#pragma unroll
    for (int mi = 0; mi < MI; mi++)
#pragma unroll
        for (int n = 0; n < 2 * NP; n++)
#pragma unroll
            for (int u = 0; u < 4; u++) acc[mi][n][u] = 0.f;

    auto copy_chunk = [&](int ch) {
        unsigned dst = sb + (unsigned)(ch & 1) * BUFB;
        const ush* sh = gh + ((size_t)ch * L + rows0) * 32;
        const ush* sl = gl + ((size_t)ch * L + rows0) * 32;
#pragma unroll
        for (int i = 0; i < PLD; i++) {
            int lin = i * 128 + tid;
            int row = lin >> 2, q = lin & 3;
            unsigned d = dst + (unsigned)(row * 64 + ((q ^ ((row >> 1) & 3)) << 4));
            cpa16(d, sh + row * 32 + q * 8);
            cpa16(d + TMB, sl + row * 32 + q * 8);
        }
        if (!diag) {
            const ush* sh2 = gh + ((size_t)ch * L + rows1) * 32;
            const ush* sl2 = gl + ((size_t)ch * L + rows1) * 32;
#pragma unroll
            for (int i = 0; i < PLD; i++) {
                int lin = i * 128 + tid;
                int row = lin >> 2, q = lin & 3;
                unsigned d = dst + 2 * TMB + (unsigned)(row * 64 + ((q ^ ((row >> 1) & 3)) << 4));
                cpa16(d, sh2 + row * 32 + q * 8);
                cpa16(d + TMB, sl2 + row * 32 + q * 8);
            }
        }
        asm volatile("cp.async.commit_group;" ::: "memory");
    };

    copy_chunk(0);
    for (int ch = 0; ch < NCH; ch++) {
        if (ch < NCH - 1) {
            copy_chunk(ch + 1);
            asm volatile("cp.async.wait_group 1;" ::: "memory");
        } else {
            asm volatile("cp.async.wait_group 0;" ::: "memory");
        }
        __syncthreads();
        unsigned abase = sb + (unsigned)(ch & 1) * BUFB;
        unsigned bbase = diag ? abase : abase + 2 * TMB;

#pragma unroll
        for (int ks = 0; ks < 2; ks++) {
            int kb = ks * 32;
            unsigned ah[MI][4], bh[NP][4];
#pragma unroll
            for (int mi = 0; mi < MI; mi++) ldsm4(ah[mi], swa(abase, m0w + mi * 16 + aro, kb + ako));
#pragma unroll
            for (int nj = 0; nj < NP; nj++) ldsm4(bh[nj], swa(bbase, j0w + nj * 16 + bro, kb + bko));
#pragma unroll
            for (int mi = 0; mi < MI; mi++)
#pragma unroll
                for (int nj = 0; nj < NP; nj++) {
                    mma16816(acc[mi][2 * nj],     ah[mi], bh[nj][0], bh[nj][1]);
                    mma16816(acc[mi][2 * nj + 1], ah[mi], bh[nj][2], bh[nj][3]);
                }
            unsigned bl[NP][4];
#pragma unroll
            for (int nj = 0; nj < NP; nj++) ldsm4(bl[nj], swa(bbase + TMB, j0w + nj * 16 + bro, kb + bko));
#pragma unroll
            for (int mi = 0; mi < MI; mi++)
#pragma unroll
                for (int nj = 0; nj < NP; nj++) {
                    mma16816(acc[mi][2 * nj],     ah[mi], bl[nj][0], bl[nj][1]);
                    mma16816(acc[mi][2 * nj + 1], ah[mi], bl[nj][2], bl[nj][3]);
                }
        }
        __syncthreads();
    }

    int rq = lane >> 2, cq = lane & 3;
#pragma unroll
    for (int mi = 0; mi < MI; mi++)
#pragma unroll
        for (int n = 0; n < 2 * NP; n++) {
            int m = rows0 + m0w + mi * 16 + rq, j = rows1 + j0w + n * 8 + cq * 2;
            *(float2*)&Gp[(size_t)m * L + j] = make_float2(acc[mi][n][0], acc[mi][n][1]);
            *(float2*)&Gp[(size_t)(m + 8) * L + j] = make_float2(acc[mi][n][2], acc[mi][n][3]);
        }
}

__global__ void __launch_bounds__(128) gram_kernel() {
    extern __shared__ __align__(16) char smraw[];
    unsigned sb = (unsigned)__cvta_generic_to_shared(smraw);
    int bid = blockIdx.x;
    if (bid < NBLK_T) {
        int seg = bid / 48, r = bid % 48, bw = r / 3, pair = r % 3;
        int which = bw >> 3, b = bw & 7;
        int pi = (pair == 2) ? 1 : 0, pj = (pair == 0) ? 0 : 1;
        const ush* gh = g_Nh[which] + (size_t)(b * 256 + seg * 32) * (LTm * 32);
        const ush* gl = g_Nl[which] + (size_t)(b * 256 + seg * 32) * (LTm * 32);
        gram_body<LTm, 96, 3, 3, 32, 3>(gh, gl, pi * 96, pj * 96, pair != 1,
                                        &g_GpT[seg][bw][0], sb);
    } else {
        int r0 = bid - NBLK_T;
        int seg = r0 / 48, r = r0 % 48, bw = r / 3, pair = r % 3;
        int which = bw >> 3, b = bw & 7;
        int pi = (pair == 2) ? 1 : 0, pj = (pair == 0) ? 0 : 1;
        const ush* gh = g_Th[which] + (size_t)(b * 384 + seg * 64) * (LFm * 32);
        const ush* gl = g_Tl[which] + (size_t)(b * 384 + seg * 64) * (LFm * 32);
        gram_body<LFm, 64, 2, 2, 64, 2>(gh, gl, pi * 64, pj * 64, pair != 1,
                                        &g_GpF[seg][bw][0], sb);
    }
}

// ---------------- 3) sum partials + mirror + fused norms ----------------
__global__ void sumG_kernel() {
    int idx = blockIdx.x * 256 + threadIdx.x;
    if (idx < NT_E) {
        int bw = idx / (LTm * LTm), e = idx % (LTm * LTm);
        int i = e / LTm, j = e % LTm;
        int es = (i >= 96 && j < 96) ? (j * LTm + i) : e;
        float s = 0.f;
#pragma unroll
        for (int g = 0; g < SEGS_T; g++) s += g_GpT[g][bw][es];
        int which = bw >> 3, b = bw & 7;
        g_G[0][which][(size_t)b * LTm * LTm + e] = s;
        if (i == j) g_inv[0][which][b * LTm + i] = 1.0f / fmaxf(sqrtf(s), 1e-8f);
    } else {
        idx -= NT_E;
        int bw = idx / (LFm * LFm), e = idx % (LFm * LFm);
        int i = e / LFm, j = e % LFm;
        int es = (i >= 64 && j < 64) ? (j * LFm + i) : e;
        float s = 0.f;
#pragma unroll
        for (int g = 0; g < SEGS_F; g++) s += g_GpF[g][bw][es];
        int which = bw >> 3, b = bw & 7;
        g_G[1][which][(size_t)b * LFm * LFm + e] = s;
        if (i == j) g_inv[1][which][b * LFm + i] = 1.0f / fmaxf(sqrtf(s), 1e-8f);
    }
}

// ---------------- 4) rowproc: warp-per-row, both views, no barriers ----------------
__global__ void rowproc2_kernel() {
    int w = blockIdx.x * 8 + (threadIdx.x >> 5);
    int lane = threadIdx.x & 31;
    int view, which, b, l, L;
    if (w < 3072) { view = 0; L = 192; which = w / 1536; int r = w % 1536; b = r / 192; l = r % 192; }
    else { int w2 = w - 3072; view = 1; L = 128; which = w2 / 1024; int r = w2 % 1024; b = r / 128; l = r % 128; }
    float* G = g_G[view][which] + ((size_t)b * L + l) * L;
    const float* inv = g_inv[view][which] + b * L;
    float invl = inv[l];
    int ne = L >> 5;
    float pv[6];
    float s = 0.f, mx = -3.402823466e38f;
    for (int e = 0; e < ne; e++) {
        int m = lane + e * 32;
        pv[e] = 0.5f * (G[m] * invl * inv[m] + 1.0f);
        s += pv[e];
        mx = fmaxf(mx, pv[e]);
    }
    s = warpSum(s);
    mx = warpMax(mx);
    if (lane == 0) g_mean[view][which][b * L + l] = s / (float)L;
    float ex[6], Z = 0.f;
    for (int e = 0; e < ne; e++) { ex[e] = expf(pv[e] - mx); Z += ex[e]; }
    Z = warpSum(Z);
    float ent = 0.f;
    for (int e = 0; e < ne; e++) {
        int m = lane + e * 32;
        float sp = ex[e] / Z + 1e-8f;
        if (which == 0) G[m] = logf(sp + 1e-8f);
        else { G[m] = sp; ent += sp * logf(sp + 1e-8f); }
    }
    if (which == 1) {
        ent = warpSum(ent);
        if (lane == 0) g_ent[view][b * L + l] = ent;
    }
}

// ---------------- 5) part2: fused MLP + alpha + rowdot + term2 ----------------
__global__ void part2_kernel(const float* __restrict__ WqT, const float* __restrict__ bqT,
                             const float* __restrict__ gqT, const float* __restrict__ BqT,
                             const float* __restrict__ WkT, const float* __restrict__ bkT,
                             const float* __restrict__ gkT, const float* __restrict__ BkT,
                             const float* __restrict__ WqF, const float* __restrict__ bqF,
                             const float* __restrict__ gqF, const float* __restrict__ BqF,
                             const float* __restrict__ WkF, const float* __restrict__ bkF,
                             const float* __restrict__ gkF, const float* __restrict__ BkF) {
    __shared__ float kb[LTm * HH];
    __shared__ float salT[LTm][8];
    __shared__ float red[8];
    __shared__ float qv8[8][HH];
    int view = blockIdx.z, b = blockIdx.y;
    int L = view ? LFm : LTm;
    if (blockIdx.x * 8 >= L) {
        if (threadIdx.x == 0) g_part[view][b * 24 + blockIdx.x] = 0.f;
        return;
    }
    int s0 = blockIdx.x * 8;
    int t = threadIdx.x;
    const float* Wq = view ? WqF : WqT; const float* bq = view ? bqF : bqT;
    const float* gq = view ? gqF : gqT; const float* Bq = view ? BqF : BqT;
    const float* Wk = view ? WkF : WkT; const float* bk = view ? bkF : bkT;
    const float* gk = view ? gkF : gkT; const float* Bk = view ? BkF : BkT;

    if (t < L) {
        float kv[HH];
        mlp4(g_mean[view][1][b * L + t], Wk, bk, gk, Bk, kv);
#pragma unroll
        for (int j = 0; j < HH; j++) kb[t * HH + j] = kv[j];
    }
    if (t < 8) {
        float qv[HH];
        mlp4(g_mean[view][0][b * L + s0 + t], Wq, bq, gq, Bq, qv);
#pragma unroll
        for (int j = 0; j < HH; j++) qv8[t][j] = qv[j];
    }
    __syncthreads();

    float entt = (t < L) ? g_ent[view][b * L + t] : 0.f;
    float k0 = 0.f, k1 = 0.f, k2 = 0.f, k3 = 0.f;
    if (t < L) { k0 = kb[t * 4 + 0]; k1 = kb[t * 4 + 1]; k2 = kb[t * 4 + 2]; k3 = kb[t * 4 + 3]; }
    float invScale = rsqrtf(4.0f + 1e-8f);
#pragma unroll
    for (int i = 0; i < 8; i++) {
        float a = -3.402823466e38f;
        if (t < L)
            a = (qv8[i][0] * k0 + qv8[i][1] * k1 + qv8[i][2] * k2 + qv8[i][3] * k3) * invScale;
        float mx = blockMax(a, red);
        float e = (t < L) ? expf(a - mx) : 0.f;
        float Z = blockSum(e, red);
        float al = e / Z;
        if (t < L) salT[t][i] = al;
        float rd = blockSum(al * entt, red);
        if (t == 0) g_rowdot[view][b * L + s0 + i] = rd;
    }
    __syncthreads();

    const float* logPs = g_G[view][0] + (size_t)b * L * L;
    const float* Pt    = g_G[view][1] + (size_t)b * L * L;
    int k = t;
    float m[8];
#pragma unroll
    for (int i = 0; i < 8; i++) m[i] = 0.f;
    int kc = (k < L) ? k : 0;
#pragma unroll 2
    for (int tt = 0; tt < L; tt++) {
        float4 a0 = *(const float4*)&salT[tt][0];
        float4 a1 = *(const float4*)&salT[tt][4];
        float pv = Pt[(size_t)tt * L + kc];
        m[0] += a0.x * pv; m[1] += a0.y * pv; m[2] += a0.z * pv; m[3] += a0.w * pv;
        m[4] += a1.x * pv; m[5] += a1.y * pv; m[6] += a1.z * pv; m[7] += a1.w * pv;
    }
    float acc = 0.f;
    if (k < L) {
#pragma unroll
        for (int i = 0; i < 8; i++) acc += m[i] * logPs[(size_t)(s0 + i) * L + k];
    }
    float tot = blockSum(acc, red);
    if (k == 0) g_part[view][b * 24 + blockIdx.x] = tot;
}

// ---------------- 6) final reduction ----------------
__global__ void final_kernel(float* out) {
    __shared__ float red[8];
    int tid = threadIdx.x;
    float t2T = 0.f; for (int i = tid; i < 24 * BB; i += 256) t2T += g_part[0][i];
    t2T = blockSum(t2T, red);
    float t2F = 0.f; for (int i = tid; i < 24 * BB; i += 256) t2F += g_part[1][i];
    t2F = blockSum(t2F, red);
    float t1T = 0.f; for (int i = tid; i < BB * LTm; i += 256) t1T += g_rowdot[0][i];
    t1T = blockSum(t1T, red);
    float t1F = 0.f; for (int i = tid; i < BB * LFm; i += 256) t1F += g_rowdot[1][i];
    t1F = blockSum(t1F, red);
    if (tid == 0) {
        float lt = (t1T - t2T) / ((float)BB * LTm * LTm + 1e-8f);
        float lf = (t1F - t2F) / ((float)BB * LFm * LFm + 1e-8f);
        out[0] = lt + lf;
    }
}

// ---------------- launch ----------------
extern "C" void kernel_launch(void* const* d_in, const int* in_sizes, int n_in,
                              void* d_out, int out_size) {
    const float* fs  = (const float*)d_in[0];
    const float* ft  = (const float*)d_in[1];
    float* out = (float*)d_out;

    prep_kernel<<<dim3(TT / 32, FFR / 32, BB * CC * 2), dim3(32, 8)>>>(fs, ft);

    gram_kernel<<<NBLK_T + NBLK_F, 128, 49152>>>();

    sumG_kernel<<<(NT_E + NF_E) / 256, 256>>>();

    rowproc2_kernel<<<640, 256>>>();

    part2_kernel<<<dim3(24, BB, 2), 192>>>(
        (const float*)d_in[2], (const float*)d_in[3], (const float*)d_in[4], (const float*)d_in[5],
        (const float*)d_in[6], (const float*)d_in[7], (const float*)d_in[8], (const float*)d_in[9],
        (const float*)d_in[10], (const float*)d_in[11], (const float*)d_in[12], (const float*)d_in[13],
        (const float*)d_in[14], (const float*)d_in[15], (const float*)d_in[16], (const float*)d_in[17]);

    final_kernel<<<1, 256>>>(out);
}